// round 14
// baseline (speedup 1.0000x reference)
#include <cuda_runtime.h>
#include <cuda_fp16.h>
#include <math.h>
#include <stdint.h>

// Problem constants (fixed by setup_inputs)
#define NTOK 8192
#define DIM  1024
#define HID  4096
#define NEXP 8
#define CAP  2560              // int(2 * 1.25 * 8192 / 8)
#define EC   (NEXP * CAP)      // 20480 dispatch rows

// ---------------- scratch (static __device__ globals; no allocs) -----------
__device__ __align__(16) float d_disp[(size_t)EC * DIM];   // 80 MB
__device__ __align__(16) float d_h   [(size_t)EC * HID];   // 320 MB
__device__ __align__(16) float d_y   [(size_t)EC * DIM];   // 80 MB

__device__ int   d_e0[NTOK], d_e1[NTOK];
__device__ float d_g0[NTOK], d_g1[NTOK];
__device__ int   d_s0[NTOK], d_s1[NTOK];     // dispatch slot or -1
__device__ float d_me[NEXP];                 // sum of softmax scores per expert
__device__ int   d_cnt0[NEXP];               // top-1 histogram (uncapped)

// ---------------- PTX helpers ----------------------------------------------
__device__ __forceinline__ uint32_t smem_u32(const void* p) {
    uint32_t a;
    asm("{ .reg .u64 t; cvta.to.shared.u64 t, %1; cvt.u32.u64 %0, t; }"
        : "=r"(a) : "l"(p));
    return a;
}
__device__ __forceinline__ void ldmat_x4(uint32_t* r, uint32_t addr) {
    asm volatile("ldmatrix.sync.aligned.m8n8.x4.shared.b16 {%0,%1,%2,%3}, [%4];"
                 : "=r"(r[0]), "=r"(r[1]), "=r"(r[2]), "=r"(r[3]) : "r"(addr));
}
__device__ __forceinline__ void ldmat_x4_t(uint32_t* r, uint32_t addr) {
    asm volatile("ldmatrix.sync.aligned.m8n8.x4.trans.shared.b16 {%0,%1,%2,%3}, [%4];"
                 : "=r"(r[0]), "=r"(r[1]), "=r"(r[2]), "=r"(r[3]) : "r"(addr));
}
__device__ __forceinline__ void mma16816(float* c, const uint32_t* a, const uint32_t* b) {
    asm volatile(
        "mma.sync.aligned.m16n8k16.row.col.f32.f16.f16.f32 "
        "{%0,%1,%2,%3}, {%4,%5,%6,%7}, {%8,%9}, {%0,%1,%2,%3};"
        : "+f"(c[0]), "+f"(c[1]), "+f"(c[2]), "+f"(c[3])
        : "r"(a[0]), "r"(a[1]), "r"(a[2]), "r"(a[3]), "r"(b[0]), "r"(b[1]));
}
__device__ __forceinline__ uint32_t pack_h2(__half a, __half b) {
    return (uint32_t)__half_as_ushort(a) | ((uint32_t)__half_as_ushort(b) << 16);
}

// ---------------- small kernels --------------------------------------------
__global__ void zero_small_kernel() {
    int t = threadIdx.x;
    if (t < NEXP) { d_me[t] = 0.0f; d_cnt0[t] = 0; }
}

__global__ void gate_kernel(const float* __restrict__ x,
                            const float* __restrict__ wg) {
    int warp = (blockIdx.x * blockDim.x + threadIdx.x) >> 5;
    int lane = threadIdx.x & 31;
    if (warp >= NTOK) return;

    const float* xr = x + (size_t)warp * DIM;
    float acc[NEXP];
#pragma unroll
    for (int e = 0; e < NEXP; e++) acc[e] = 0.0f;
    for (int d = lane; d < DIM; d += 32) {
        float xv = xr[d];
        const float* w = wg + (size_t)d * NEXP;
#pragma unroll
        for (int e = 0; e < NEXP; e++) acc[e] += xv * w[e];
    }
#pragma unroll
    for (int off = 16; off > 0; off >>= 1)
#pragma unroll
        for (int e = 0; e < NEXP; e++)
            acc[e] += __shfl_xor_sync(0xFFFFFFFFu, acc[e], off);

    if (lane == 0) {
        float m = acc[0];
#pragma unroll
        for (int e = 1; e < NEXP; e++) m = fmaxf(m, acc[e]);
        float p[NEXP], s = 0.0f;
#pragma unroll
        for (int e = 0; e < NEXP; e++) { p[e] = expf(acc[e] - m); s += p[e]; }
        float inv = 1.0f / s;
#pragma unroll
        for (int e = 0; e < NEXP; e++) p[e] *= inv;

        float best = -1.0f, second = -1.0f;
        int e0 = 0, e1 = 0;
#pragma unroll
        for (int e = 0; e < NEXP; e++) {
            float v = p[e];
            if (v > best)        { second = best; e1 = e0; best = v; e0 = e; }
            else if (v > second) { second = v; e1 = e; }
        }
        d_e0[warp] = e0; d_e1[warp] = e1;
        d_g0[warp] = best; d_g1[warp] = second;
#pragma unroll
        for (int e = 0; e < NEXP; e++) atomicAdd(&d_me[e], p[e]);
        atomicAdd(&d_cnt0[e0], 1);
    }
}

__global__ void rank_kernel() {
    __shared__ int   se0[256]; __shared__ float sg0[256];
    __shared__ int   se1[256]; __shared__ float sg1[256];

    int i = blockIdx.x * 256 + threadIdx.x;
    int   my_e0 = d_e0[i], my_e1 = d_e1[i];
    float my_g0 = d_g0[i], my_g1 = d_g1[i];
    int r0 = 0, r1 = 0;

    for (int base = 0; base < NTOK; base += 256) {
        int t = base + threadIdx.x;
        se0[threadIdx.x] = d_e0[t]; sg0[threadIdx.x] = d_g0[t];
        se1[threadIdx.x] = d_e1[t]; sg1[threadIdx.x] = d_g1[t];
        __syncthreads();
#pragma unroll 8
        for (int k = 0; k < 256; k++) {
            int tp = base + k;
            r0 += (se0[k] == my_e0) && (sg0[k] > my_g0 || (sg0[k] == my_g0 && tp < i));
            r1 += (se1[k] == my_e1) && (sg1[k] > my_g1 || (sg1[k] == my_g1 && tp < i));
        }
        __syncthreads();
    }
    int pos0 = r0;
    int pos1 = r1 + d_cnt0[my_e1];
    d_s0[i] = (pos0 < CAP) ? my_e0 * CAP + pos0 : -1;
    d_s1[i] = (pos1 < CAP) ? my_e1 * CAP + pos1 : -1;
}

// fp32 scatter (identical to passing round-13 version)
__global__ void scatter_kernel(const float* __restrict__ x) {
    int i = blockIdx.x;
    int s0 = d_s0[i], s1 = d_s1[i];
    if (s0 < 0 && s1 < 0) return;
    float4 v = ((const float4*)(x + (size_t)i * DIM))[threadIdx.x];
    if (s0 >= 0) ((float4*)(d_disp + (size_t)s0 * DIM))[threadIdx.x] = v;
    if (s1 >= 0) ((float4*)(d_disp + (size_t)s1 * DIM))[threadIdx.x] = v;
}

__device__ __forceinline__ float gelu_exact(float v) {
    return 0.5f * v * (1.0f + erff(v * 0.70710678118654752f));
}

// ---------------- mma.sync 1-term fp16 GEMM, 256x128 tile ------------------
// Block tile 256m x 128n, 8 warps (warp tile 64m x 64n, 4x2), K-chunk 32,
// single smem stage + LDG register prefetch (proven R13 structure).
// A fp32 [m][k] rounded in-kernel to fp16; B fp32 [e][k][n] rounded to fp16.
// C = Ah * Bh, fp32 accum.
#define A_STRIDE 40     // halves per A row (80 B, 16B-aligned, conflict-free)
#define B_STRIDE 136    // halves per B row (272 B, 16B-aligned, conflict-free)

template<int KTOT, int NTOT, bool FC1>
__global__ void __launch_bounds__(256)
mma_gemm_kernel(const float* __restrict__ W, const float* __restrict__ bias) {
    __shared__ __half sAh[256 * A_STRIDE];   // 20480 B
    __shared__ __half sBh[32 * B_STRIDE];    //  8704 B  (total 29184 B static)

    const float* __restrict__ A = FC1 ? d_disp : d_h;
    int tid = threadIdx.x;
    int wid = tid >> 5, lane = tid & 31;
    int wm = wid & 3, wn = wid >> 2;          // warp tile 64m x 64n (4x2)

    int row0 = blockIdx.y * 256;
    int n0   = blockIdx.x * 128;
    int e    = row0 / CAP;                    // 256 | CAP
    const float* Ap = A + (size_t)row0 * KTOT;
    const float* Bp = W + (size_t)e * KTOT * NTOT;
    const float* bp = bias + (size_t)e * NTOT;

    uint32_t aAh = smem_u32(sAh);
    uint32_t aBh = smem_u32(sBh);

    float acc[4][8][4];
#pragma unroll
    for (int mi = 0; mi < 4; mi++)
#pragma unroll
        for (int ni = 0; ni < 8; ni++)
#pragma unroll
            for (int q = 0; q < 4; q++) acc[mi][ni][q] = 0.0f;

    const int arow = tid >> 3;            // 0..31  (A: 256 rows via 8 its)
    const int ac4  = (tid & 7) * 4;       // 0..28
    const int brow = tid >> 3;            // 0..31  (B: 32 k rows)
    const int bc4  = (tid & 7) * 4;       // base col (4 its * 32)

    constexpr int NCH = KTOT / 32;

    float4 aReg[8], bReg[4];
    // prologue: load chunk 0 into registers
#pragma unroll
    for (int it = 0; it < 8; it++)
        aReg[it] = *(const float4*)(Ap + (size_t)(arow + it * 32) * KTOT + ac4);
#pragma unroll
    for (int it = 0; it < 4; it++)
        bReg[it] = *(const float4*)(Bp + (size_t)brow * NTOT + n0 + bc4 + it * 32);

    for (int ch = 0; ch < NCH; ch++) {
        // ---- round regs -> smem ----
#pragma unroll
        for (int it = 0; it < 8; it++) {
            int r = arow + it * 32;
            float4 v = aReg[it];
            *(uint2*)&sAh[r * A_STRIDE + ac4] =
                make_uint2(pack_h2(__float2half(v.x), __float2half(v.y)),
                           pack_h2(__float2half(v.z), __float2half(v.w)));
        }
#pragma unroll
        for (int it = 0; it < 4; it++) {
            int c = bc4 + it * 32;
            float4 v = bReg[it];
            *(uint2*)&sBh[brow * B_STRIDE + c] =
                make_uint2(pack_h2(__float2half(v.x), __float2half(v.y)),
                           pack_h2(__float2half(v.z), __float2half(v.w)));
        }
        __syncthreads();

        // ---- prefetch next chunk into registers (LDG in flight over compute) ----
        if (ch + 1 < NCH) {
            int kn = (ch + 1) * 32;
#pragma unroll
            for (int it = 0; it < 8; it++)
                aReg[it] = *(const float4*)(Ap + (size_t)(arow + it * 32) * KTOT + kn + ac4);
#pragma unroll
            for (int it = 0; it < 4; it++)
                bReg[it] = *(const float4*)(Bp + (size_t)(kn + brow) * NTOT + n0 + bc4 + it * 32);
        }

        // ---- compute: 2 k16 steps ----
#pragma unroll
        for (int ks = 0; ks < 2; ks++) {
            uint32_t ah[4][4];
#pragma unroll
            for (int mi = 0; mi < 4; mi++) {
                int r = wm * 64 + mi * 16 + (lane & 15);
                uint32_t off = (uint32_t)(r * (A_STRIDE * 2) + ks * 32 + ((lane >> 4) << 4));
                ldmat_x4(ah[mi], aAh + off);
            }
#pragma unroll
            for (int p = 0; p < 4; p++) {
                int j = lane >> 3, i = lane & 7;
                int kk = ks * 16 + (j & 1) * 8 + i;
                int nn = wn * 64 + p * 16 + (j >> 1) * 8;
                uint32_t off = (uint32_t)(kk * (B_STRIDE * 2) + nn * 2);
                uint32_t b4[4];
                ldmat_x4_t(b4, aBh + off);
#pragma unroll
                for (int ni2 = 0; ni2 < 2; ni2++) {
                    int ni = p * 2 + ni2;
                    const uint32_t* bp2 = &b4[ni2 * 2];
#pragma unroll
                    for (int mi = 0; mi < 4; mi++)
                        mma16816(acc[mi][ni], ah[mi], bp2);
                }
            }
        }
        __syncthreads();
    }

    // ---- epilogue: bias (+gelu for FC1), fp32 stores ----
#pragma unroll
    for (int mi = 0; mi < 4; mi++) {
        int rbase = row0 + wm * 64 + mi * 16 + (lane >> 2);
#pragma unroll
        for (int ni = 0; ni < 8; ni++) {
            int col_l = wn * 64 + ni * 8 + ((lane & 3) << 1);
            float b0 = bp[n0 + col_l], b1 = bp[n0 + col_l + 1];
#pragma unroll
            for (int hh = 0; hh < 2; hh++) {
                int row = rbase + hh * 8;
                float v0 = acc[mi][ni][hh * 2]     + b0;
                float v1 = acc[mi][ni][hh * 2 + 1] + b1;
                size_t g = (size_t)row * NTOT + n0 + col_l;
                if (FC1) {
                    v0 = gelu_exact(v0); v1 = gelu_exact(v1);
                    *(float2*)(d_h + g) = make_float2(v0, v1);
                } else {
                    *(float2*)(d_y + g) = make_float2(v0, v1);
                }
            }
        }
    }
}

// out[i] = w0 * Y[s0] + w1 * Y[s1]
__global__ void combine_kernel(float* __restrict__ out) {
    int i = blockIdx.x;
    int s0 = d_s0[i], s1 = d_s1[i];
    float w0 = (s0 >= 0) ? d_g0[i] : 0.0f;
    float w1 = (s1 >= 0) ? d_g1[i] : 0.0f;
    float4 r = make_float4(0.f, 0.f, 0.f, 0.f);
    if (s0 >= 0) {
        float4 a = ((const float4*)(d_y + (size_t)s0 * DIM))[threadIdx.x];
        r.x += w0 * a.x; r.y += w0 * a.y; r.z += w0 * a.z; r.w += w0 * a.w;
    }
    if (s1 >= 0) {
        float4 a = ((const float4*)(d_y + (size_t)s1 * DIM))[threadIdx.x];
        r.x += w1 * a.x; r.y += w1 * a.y; r.z += w1 * a.z; r.w += w1 * a.w;
    }
    ((float4*)(out + (size_t)i * DIM))[threadIdx.x] = r;
}

__global__ void laux_kernel(float* __restrict__ out, int out_size) {
    if (threadIdx.x == 0 && out_size > NTOK * DIM) {
        float lx = 0.0f;
        for (int e = 0; e < NEXP; e++) {
            float me = d_me[e] / (float)NTOK;
            float ce = (float)d_cnt0[e] / (float)NTOK;
            lx += me * ce;
        }
        out[NTOK * DIM] = lx * (float)NEXP;
    }
}

// ---------------- launch ---------------------------------------------------
extern "C" void kernel_launch(void* const* d_in, const int* in_sizes, int n_in,
                              void* d_out, int out_size) {
    const float* x     = (const float*)d_in[0];
    const float* wg    = (const float*)d_in[1];
    const float* fc1_w = (const float*)d_in[2];
    const float* fc1_b = (const float*)d_in[3];
    const float* fc2_w = (const float*)d_in[4];
    const float* fc2_b = (const float*)d_in[5];
    float* out = (float*)d_out;

    zero_small_kernel<<<1, 32>>>();
    gate_kernel<<<NTOK / 8, 256>>>(x, wg);
    rank_kernel<<<NTOK / 256, 256>>>();
    scatter_kernel<<<NTOK, 256>>>(x);

    // FC1: A=d_disp [EC][DIM], B=fc1_w [E][DIM][HID] -> d_h (gelu+bias)
    mma_gemm_kernel<DIM, HID, true><<<dim3(HID / 128, EC / 256), 256>>>(fc1_w, fc1_b);
    // FC2: A=d_h [EC][HID],   B=fc2_w [E][HID][DIM] -> d_y (bias)
    mma_gemm_kernel<HID, DIM, false><<<dim3(DIM / 128, EC / 256), 256>>>(fc2_w, fc2_b);

    combine_kernel<<<NTOK, 256>>>(out);
    laux_kernel<<<1, 32>>>(out, out_size);
}

// round 15
// speedup vs baseline: 1.1908x; 1.1908x over previous
#include <cuda_runtime.h>
#include <cuda_fp16.h>
#include <math.h>
#include <stdint.h>

// Problem constants (fixed by setup_inputs)
#define NTOK 8192
#define DIM  1024
#define HID  4096
#define NEXP 8
#define CAP  2560              // int(2 * 1.25 * 8192 / 8)
#define EC   (NEXP * CAP)      // 20480 dispatch rows

// ---------------- scratch (static __device__ globals; no allocs) -----------
// NOTE: __device__ globals are ONLY referenced inside device code. Passing
// them as kernel arguments from host code passes the host shadow address —
// the root cause of every zero-output failure in rounds 5/7/10/12.
__device__ __align__(16) __half d_disp16[(size_t)EC * DIM];      // 40 MB
__device__ __align__(16) __half d_h16[(size_t)EC * HID];         // 168 MB
__device__ __align__(16) float  d_y[(size_t)EC * DIM];           // 80 MB
__device__ __align__(16) __half d_w1h[(size_t)NEXP * DIM * HID]; // 64 MB [e][k][n]
__device__ __align__(16) __half d_w2h[(size_t)NEXP * DIM * HID]; // 64 MB [e][k][n]

__device__ int   d_e0[NTOK], d_e1[NTOK];
__device__ float d_g0[NTOK], d_g1[NTOK];
__device__ int   d_s0[NTOK], d_s1[NTOK];     // dispatch slot or -1
__device__ float d_me[NEXP];                 // sum of softmax scores per expert
__device__ int   d_cnt0[NEXP];               // top-1 histogram (uncapped)

// ---------------- PTX helpers ----------------------------------------------
__device__ __forceinline__ uint32_t smem_u32(const void* p) {
    uint32_t a;
    asm("{ .reg .u64 t; cvta.to.shared.u64 t, %1; cvt.u32.u64 %0, t; }"
        : "=r"(a) : "l"(p));
    return a;
}
__device__ __forceinline__ void ldmat_x4(uint32_t* r, uint32_t addr) {
    asm volatile("ldmatrix.sync.aligned.m8n8.x4.shared.b16 {%0,%1,%2,%3}, [%4];"
                 : "=r"(r[0]), "=r"(r[1]), "=r"(r[2]), "=r"(r[3]) : "r"(addr));
}
__device__ __forceinline__ void ldmat_x4_t(uint32_t* r, uint32_t addr) {
    asm volatile("ldmatrix.sync.aligned.m8n8.x4.trans.shared.b16 {%0,%1,%2,%3}, [%4];"
                 : "=r"(r[0]), "=r"(r[1]), "=r"(r[2]), "=r"(r[3]) : "r"(addr));
}
__device__ __forceinline__ void mma16816(float* c, const uint32_t* a, const uint32_t* b) {
    asm volatile(
        "mma.sync.aligned.m16n8k16.row.col.f32.f16.f16.f32 "
        "{%0,%1,%2,%3}, {%4,%5,%6,%7}, {%8,%9}, {%0,%1,%2,%3};"
        : "+f"(c[0]), "+f"(c[1]), "+f"(c[2]), "+f"(c[3])
        : "r"(a[0]), "r"(a[1]), "r"(a[2]), "r"(a[3]), "r"(b[0]), "r"(b[1]));
}
__device__ __forceinline__ uint32_t pack_h2(__half a, __half b) {
    return (uint32_t)__half_as_ushort(a) | ((uint32_t)__half_as_ushort(b) << 16);
}

// ---------------- small kernels --------------------------------------------
__global__ void zero_small_kernel() {
    int t = threadIdx.x;
    if (t < NEXP) { d_me[t] = 0.0f; d_cnt0[t] = 0; }
}

__global__ void gate_kernel(const float* __restrict__ x,
                            const float* __restrict__ wg) {
    int warp = (blockIdx.x * blockDim.x + threadIdx.x) >> 5;
    int lane = threadIdx.x & 31;
    if (warp >= NTOK) return;

    const float* xr = x + (size_t)warp * DIM;
    float acc[NEXP];
#pragma unroll
    for (int e = 0; e < NEXP; e++) acc[e] = 0.0f;
    for (int d = lane; d < DIM; d += 32) {
        float xv = xr[d];
        const float* w = wg + (size_t)d * NEXP;
#pragma unroll
        for (int e = 0; e < NEXP; e++) acc[e] += xv * w[e];
    }
#pragma unroll
    for (int off = 16; off > 0; off >>= 1)
#pragma unroll
        for (int e = 0; e < NEXP; e++)
            acc[e] += __shfl_xor_sync(0xFFFFFFFFu, acc[e], off);

    if (lane == 0) {
        float m = acc[0];
#pragma unroll
        for (int e = 1; e < NEXP; e++) m = fmaxf(m, acc[e]);
        float p[NEXP], s = 0.0f;
#pragma unroll
        for (int e = 0; e < NEXP; e++) { p[e] = expf(acc[e] - m); s += p[e]; }
        float inv = 1.0f / s;
#pragma unroll
        for (int e = 0; e < NEXP; e++) p[e] *= inv;

        float best = -1.0f, second = -1.0f;
        int e0 = 0, e1 = 0;
#pragma unroll
        for (int e = 0; e < NEXP; e++) {
            float v = p[e];
            if (v > best)        { second = best; e1 = e0; best = v; e0 = e; }
            else if (v > second) { second = v; e1 = e; }
        }
        d_e0[warp] = e0; d_e1[warp] = e1;
        d_g0[warp] = best; d_g1[warp] = second;
#pragma unroll
        for (int e = 0; e < NEXP; e++) atomicAdd(&d_me[e], p[e]);
        atomicAdd(&d_cnt0[e0], 1);
    }
}

__global__ void rank_kernel() {
    __shared__ int   se0[256]; __shared__ float sg0[256];
    __shared__ int   se1[256]; __shared__ float sg1[256];

    int i = blockIdx.x * 256 + threadIdx.x;
    int   my_e0 = d_e0[i], my_e1 = d_e1[i];
    float my_g0 = d_g0[i], my_g1 = d_g1[i];
    int r0 = 0, r1 = 0;

    for (int base = 0; base < NTOK; base += 256) {
        int t = base + threadIdx.x;
        se0[threadIdx.x] = d_e0[t]; sg0[threadIdx.x] = d_g0[t];
        se1[threadIdx.x] = d_e1[t]; sg1[threadIdx.x] = d_g1[t];
        __syncthreads();
#pragma unroll 8
        for (int k = 0; k < 256; k++) {
            int tp = base + k;
            r0 += (se0[k] == my_e0) && (sg0[k] > my_g0 || (sg0[k] == my_g0 && tp < i));
            r1 += (se1[k] == my_e1) && (sg1[k] > my_g1 || (sg1[k] == my_g1 && tp < i));
        }
        __syncthreads();
    }
    int pos0 = r0;
    int pos1 = r1 + d_cnt0[my_e1];
    d_s0[i] = (pos0 < CAP) ? my_e0 * CAP + pos0 : -1;
    d_s1[i] = (pos1 < CAP) ? my_e1 * CAP + pos1 : -1;
}

// scatter: token rows -> dispatch buffer, fp16 (globals referenced in-kernel)
__global__ void scatter_kernel(const float* __restrict__ x) {
    int i = blockIdx.x;
    int s0 = d_s0[i], s1 = d_s1[i];
    if (s0 < 0 && s1 < 0) return;
    float4 v = ((const float4*)(x + (size_t)i * DIM))[threadIdx.x];
    uint2 hp = make_uint2(pack_h2(__float2half(v.x), __float2half(v.y)),
                          pack_h2(__float2half(v.z), __float2half(v.w)));
    if (s0 >= 0) ((uint2*)(d_disp16 + (size_t)s0 * DIM))[threadIdx.x] = hp;
    if (s1 >= 0) ((uint2*)(d_disp16 + (size_t)s1 * DIM))[threadIdx.x] = hp;
}

// weights: fp32 -> fp16, layout preserved; dst global selected by template
template<bool W1>
__global__ void wconv_kernel(const float* __restrict__ src) {
    __half* dst = W1 ? d_w1h : d_w2h;
    int i = blockIdx.x * blockDim.x + threadIdx.x;
    float2 v = ((const float2*)src)[i];
    ((uint32_t*)dst)[i] = pack_h2(__float2half(v.x), __float2half(v.y));
}

__device__ __forceinline__ float gelu_exact(float v) {
    return 0.5f * v * (1.0f + erff(v * 0.70710678118654752f));
}

// ---------------- mma.sync fp16 GEMM, static smem, reg prefetch -------------
// Block tile 128x128, 8 warps (warp 64m x 32n), K-chunk 64, single smem stage
// + LDG.128 register prefetch (proven R13 structure, fp16 globals).
// A fp16 [m][k] (disp16 or h16); B fp16 [e][k][n] (w1h/w2h). fp32 accum.
#define KC    64
#define A_ST  72     // halves per A row (144 B; 16B-aligned, LDSM conflict-free)
#define B_ST  136    // halves per B row (272 B; 16B-aligned, LDSM conflict-free)

template<int KTOT, int NTOT, bool FC1>
__global__ void __launch_bounds__(256)
mma_gemm_kernel(const float* __restrict__ bias) {
    __shared__ __half sA[128 * A_ST];   // 18432 B
    __shared__ __half sB[KC * B_ST];    // 17408 B  (35840 B static)

    const __half* __restrict__ Ag = FC1 ? d_disp16 : d_h16;
    const __half* __restrict__ Bg = FC1 ? d_w1h    : d_w2h;

    int tid = threadIdx.x;
    int wid = tid >> 5, lane = tid & 31;
    int wm = wid & 1, wn = wid >> 1;          // warp tile 64m x 32n

    int row0 = blockIdx.y * 128;
    int n0   = blockIdx.x * 128;
    int e    = row0 / CAP;                    // 128 | CAP
    const __half* Ap = Ag + (size_t)row0 * KTOT;
    const __half* Bp = Bg + (size_t)e * KTOT * NTOT;
    const float*  bp = bias + (size_t)e * NTOT;

    uint32_t aA = smem_u32(sA), aB = smem_u32(sB);

    float acc[4][4][4];
#pragma unroll
    for (int mi = 0; mi < 4; mi++)
#pragma unroll
        for (int ni = 0; ni < 4; ni++)
#pragma unroll
            for (int q = 0; q < 4; q++) acc[mi][ni][q] = 0.0f;

    // load coords: A = 128 rows x 8 vec8 (2048 v8 / 256 thr = 4 iters over rows)
    //              B = 64 rows x 16 vec8 (1024 v8 / 256 thr = 4 iters over rows)
    const int arow = tid >> 3, acol = (tid & 7) * 8;
    const int brow = tid >> 4, bcol = (tid & 15) * 8;

    constexpr int NCH = KTOT / KC;

    uint4 aReg[4], bReg[4];
#pragma unroll
    for (int it = 0; it < 4; it++)
        aReg[it] = *(const uint4*)(Ap + (size_t)(arow + it * 32) * KTOT + acol);
#pragma unroll
    for (int it = 0; it < 4; it++)
        bReg[it] = *(const uint4*)(Bp + (size_t)(brow + it * 16) * NTOT + n0 + bcol);

    for (int ch = 0; ch < NCH; ch++) {
        // ---- regs -> smem ----
#pragma unroll
        for (int it = 0; it < 4; it++)
            *(uint4*)&sA[(arow + it * 32) * A_ST + acol] = aReg[it];
#pragma unroll
        for (int it = 0; it < 4; it++)
            *(uint4*)&sB[(brow + it * 16) * B_ST + bcol] = bReg[it];
        __syncthreads();

        // ---- prefetch next chunk (LDG in flight over compute) ----
        if (ch + 1 < NCH) {
            int kn = (ch + 1) * KC;
#pragma unroll
            for (int it = 0; it < 4; it++)
                aReg[it] = *(const uint4*)(Ap + (size_t)(arow + it * 32) * KTOT + kn + acol);
#pragma unroll
            for (int it = 0; it < 4; it++)
                bReg[it] = *(const uint4*)(Bp + (size_t)(kn + brow + it * 16) * NTOT + n0 + bcol);
        }

        // ---- compute: 4 k16 steps ----
#pragma unroll
        for (int ks = 0; ks < 4; ks++) {
            uint32_t af[4][4];
#pragma unroll
            for (int mi = 0; mi < 4; mi++) {
                int r = wm * 64 + mi * 16 + (lane & 15);
                uint32_t off = (uint32_t)(r * (A_ST * 2) + ks * 32 + ((lane >> 4) << 4));
                ldmat_x4(af[mi], aA + off);
            }
#pragma unroll
            for (int p = 0; p < 2; p++) {
                int j = lane >> 3, i = lane & 7;
                int kk = ks * 16 + (j & 1) * 8 + i;
                int nn = wn * 32 + p * 16 + (j >> 1) * 8;
                uint32_t off = (uint32_t)(kk * (B_ST * 2) + nn * 2);
                uint32_t b4[4];
                ldmat_x4_t(b4, aB + off);
#pragma unroll
                for (int ni2 = 0; ni2 < 2; ni2++) {
                    int ni = p * 2 + ni2;
                    const uint32_t* bp2 = &b4[ni2 * 2];
#pragma unroll
                    for (int mi = 0; mi < 4; mi++)
                        mma16816(acc[mi][ni], af[mi], bp2);
                }
            }
        }
        __syncthreads();
    }

    // ---- epilogue: bias (+gelu for FC1) ----
#pragma unroll
    for (int mi = 0; mi < 4; mi++) {
        int rbase = row0 + wm * 64 + mi * 16 + (lane >> 2);
#pragma unroll
        for (int ni = 0; ni < 4; ni++) {
            int col_l = wn * 32 + ni * 8 + ((lane & 3) << 1);
            float b0 = bp[n0 + col_l], b1 = bp[n0 + col_l + 1];
#pragma unroll
            for (int hh = 0; hh < 2; hh++) {
                int row = rbase + hh * 8;
                float v0 = acc[mi][ni][hh * 2]     + b0;
                float v1 = acc[mi][ni][hh * 2 + 1] + b1;
                size_t g = (size_t)row * NTOT + n0 + col_l;
                if (FC1) {
                    v0 = gelu_exact(v0); v1 = gelu_exact(v1);
                    *(uint32_t*)(d_h16 + g) =
                        pack_h2(__float2half(v0), __float2half(v1));
                } else {
                    *(float2*)(d_y + g) = make_float2(v0, v1);
                }
            }
        }
    }
}

// out[i] = w0 * Y[s0] + w1 * Y[s1]
__global__ void combine_kernel(float* __restrict__ out) {
    int i = blockIdx.x;
    int s0 = d_s0[i], s1 = d_s1[i];
    float w0 = (s0 >= 0) ? d_g0[i] : 0.0f;
    float w1 = (s1 >= 0) ? d_g1[i] : 0.0f;
    float4 r = make_float4(0.f, 0.f, 0.f, 0.f);
    if (s0 >= 0) {
        float4 a = ((const float4*)(d_y + (size_t)s0 * DIM))[threadIdx.x];
        r.x += w0 * a.x; r.y += w0 * a.y; r.z += w0 * a.z; r.w += w0 * a.w;
    }
    if (s1 >= 0) {
        float4 a = ((const float4*)(d_y + (size_t)s1 * DIM))[threadIdx.x];
        r.x += w1 * a.x; r.y += w1 * a.y; r.z += w1 * a.z; r.w += w1 * a.w;
    }
    ((float4*)(out + (size_t)i * DIM))[threadIdx.x] = r;
}

__global__ void laux_kernel(float* __restrict__ out, int out_size) {
    if (threadIdx.x == 0 && out_size > NTOK * DIM) {
        float lx = 0.0f;
        for (int e = 0; e < NEXP; e++) {
            float me = d_me[e] / (float)NTOK;
            float ce = (float)d_cnt0[e] / (float)NTOK;
            lx += me * ce;
        }
        out[NTOK * DIM] = lx * (float)NEXP;
    }
}

// ---------------- launch ---------------------------------------------------
extern "C" void kernel_launch(void* const* d_in, const int* in_sizes, int n_in,
                              void* d_out, int out_size) {
    const float* x     = (const float*)d_in[0];
    const float* wg    = (const float*)d_in[1];
    const float* fc1_w = (const float*)d_in[2];
    const float* fc1_b = (const float*)d_in[3];
    const float* fc2_w = (const float*)d_in[4];
    const float* fc2_b = (const float*)d_in[5];
    float* out = (float*)d_out;

    zero_small_kernel<<<1, 32>>>();
    gate_kernel<<<NTOK / 8, 256>>>(x, wg);
    rank_kernel<<<NTOK / 256, 256>>>();
    scatter_kernel<<<NTOK, 256>>>(x);

    const int wtot2 = NEXP * DIM * HID / 2;
    wconv_kernel<true ><<<wtot2 / 256, 256>>>(fc1_w);
    wconv_kernel<false><<<wtot2 / 256, 256>>>(fc2_w);

    // FC1: A=disp16 [EC][DIM], B=w1h [E][DIM][HID] -> h16 (bias+gelu)
    mma_gemm_kernel<DIM, HID, true><<<dim3(HID / 128, EC / 128), 256>>>(fc1_b);
    // FC2: A=h16 [EC][HID], B=w2h [E][HID][DIM] -> y fp32 (bias)
    mma_gemm_kernel<HID, DIM, false><<<dim3(DIM / 128, EC / 128), 256>>>(fc2_b);

    combine_kernel<<<NTOK, 256>>>(out);
    laux_kernel<<<1, 32>>>(out, out_size);
}

// round 16
// speedup vs baseline: 1.2391x; 1.0406x over previous
#include <cuda_runtime.h>
#include <cuda_fp16.h>
#include <math.h>
#include <stdint.h>

// Problem constants (fixed by setup_inputs)
#define NTOK 8192
#define DIM  1024
#define HID  4096
#define NEXP 8
#define CAP  2560              // int(2 * 1.25 * 8192 / 8)
#define EC   (NEXP * CAP)      // 20480 dispatch rows

// ---------------- scratch (static __device__ globals; no allocs) -----------
// NOTE: __device__ globals are ONLY referenced inside device code (passing
// them as host-side kernel args passes the host shadow address — root cause
// of the round-5/7/10/12 zero-output failures).
__device__ __align__(16) __half d_disp16[(size_t)EC * DIM];      // 40 MB
__device__ __align__(16) __half d_h16[(size_t)EC * HID];         // 168 MB
__device__ __align__(16) float  d_y[(size_t)EC * DIM];           // 80 MB
__device__ __align__(16) __half d_w1h[(size_t)NEXP * DIM * HID]; // 64 MB [e][k][n]
__device__ __align__(16) __half d_w2h[(size_t)NEXP * DIM * HID]; // 64 MB [e][k][n]

__device__ int   d_e0[NTOK], d_e1[NTOK];
__device__ float d_g0[NTOK], d_g1[NTOK];
__device__ int   d_s0[NTOK], d_s1[NTOK];     // dispatch slot or -1
__device__ float d_me[NEXP];                 // sum of softmax scores per expert
__device__ int   d_cnt0[NEXP];               // top-1 histogram (uncapped)

// ---------------- PTX helpers ----------------------------------------------
__device__ __forceinline__ uint32_t smem_u32(const void* p) {
    uint32_t a;
    asm("{ .reg .u64 t; cvta.to.shared.u64 t, %1; cvt.u32.u64 %0, t; }"
        : "=r"(a) : "l"(p));
    return a;
}
__device__ __forceinline__ void ldmat_x4(uint32_t* r, uint32_t addr) {
    asm volatile("ldmatrix.sync.aligned.m8n8.x4.shared.b16 {%0,%1,%2,%3}, [%4];"
                 : "=r"(r[0]), "=r"(r[1]), "=r"(r[2]), "=r"(r[3]) : "r"(addr));
}
__device__ __forceinline__ void ldmat_x4_t(uint32_t* r, uint32_t addr) {
    asm volatile("ldmatrix.sync.aligned.m8n8.x4.trans.shared.b16 {%0,%1,%2,%3}, [%4];"
                 : "=r"(r[0]), "=r"(r[1]), "=r"(r[2]), "=r"(r[3]) : "r"(addr));
}
__device__ __forceinline__ void mma16816(float* c, const uint32_t* a, const uint32_t* b) {
    asm volatile(
        "mma.sync.aligned.m16n8k16.row.col.f32.f16.f16.f32 "
        "{%0,%1,%2,%3}, {%4,%5,%6,%7}, {%8,%9}, {%0,%1,%2,%3};"
        : "+f"(c[0]), "+f"(c[1]), "+f"(c[2]), "+f"(c[3])
        : "r"(a[0]), "r"(a[1]), "r"(a[2]), "r"(a[3]), "r"(b[0]), "r"(b[1]));
}
__device__ __forceinline__ uint32_t pack_h2(__half a, __half b) {
    return (uint32_t)__half_as_ushort(a) | ((uint32_t)__half_as_ushort(b) << 16);
}

// ---------------- small kernels --------------------------------------------
__global__ void zero_small_kernel() {
    int t = threadIdx.x;
    if (t < NEXP) { d_me[t] = 0.0f; d_cnt0[t] = 0; }
}

__global__ void gate_kernel(const float* __restrict__ x,
                            const float* __restrict__ wg) {
    int warp = (blockIdx.x * blockDim.x + threadIdx.x) >> 5;
    int lane = threadIdx.x & 31;
    if (warp >= NTOK) return;

    const float* xr = x + (size_t)warp * DIM;
    float acc[NEXP];
#pragma unroll
    for (int e = 0; e < NEXP; e++) acc[e] = 0.0f;
    for (int d = lane; d < DIM; d += 32) {
        float xv = xr[d];
        const float* w = wg + (size_t)d * NEXP;
#pragma unroll
        for (int e = 0; e < NEXP; e++) acc[e] += xv * w[e];
    }
#pragma unroll
    for (int off = 16; off > 0; off >>= 1)
#pragma unroll
        for (int e = 0; e < NEXP; e++)
            acc[e] += __shfl_xor_sync(0xFFFFFFFFu, acc[e], off);

    if (lane == 0) {
        float m = acc[0];
#pragma unroll
        for (int e = 1; e < NEXP; e++) m = fmaxf(m, acc[e]);
        float p[NEXP], s = 0.0f;
#pragma unroll
        for (int e = 0; e < NEXP; e++) { p[e] = expf(acc[e] - m); s += p[e]; }
        float inv = 1.0f / s;
#pragma unroll
        for (int e = 0; e < NEXP; e++) p[e] *= inv;

        float best = -1.0f, second = -1.0f;
        int e0 = 0, e1 = 0;
#pragma unroll
        for (int e = 0; e < NEXP; e++) {
            float v = p[e];
            if (v > best)        { second = best; e1 = e0; best = v; e0 = e; }
            else if (v > second) { second = v; e1 = e; }
        }
        d_e0[warp] = e0; d_e1[warp] = e1;
        d_g0[warp] = best; d_g1[warp] = second;
#pragma unroll
        for (int e = 0; e < NEXP; e++) atomicAdd(&d_me[e], p[e]);
        atomicAdd(&d_cnt0[e0], 1);
    }
}

__global__ void rank_kernel() {
    __shared__ int   se0[256]; __shared__ float sg0[256];
    __shared__ int   se1[256]; __shared__ float sg1[256];

    int i = blockIdx.x * 256 + threadIdx.x;
    int   my_e0 = d_e0[i], my_e1 = d_e1[i];
    float my_g0 = d_g0[i], my_g1 = d_g1[i];
    int r0 = 0, r1 = 0;

    for (int base = 0; base < NTOK; base += 256) {
        int t = base + threadIdx.x;
        se0[threadIdx.x] = d_e0[t]; sg0[threadIdx.x] = d_g0[t];
        se1[threadIdx.x] = d_e1[t]; sg1[threadIdx.x] = d_g1[t];
        __syncthreads();
#pragma unroll 8
        for (int k = 0; k < 256; k++) {
            int tp = base + k;
            r0 += (se0[k] == my_e0) && (sg0[k] > my_g0 || (sg0[k] == my_g0 && tp < i));
            r1 += (se1[k] == my_e1) && (sg1[k] > my_g1 || (sg1[k] == my_g1 && tp < i));
        }
        __syncthreads();
    }
    int pos0 = r0;
    int pos1 = r1 + d_cnt0[my_e1];
    d_s0[i] = (pos0 < CAP) ? my_e0 * CAP + pos0 : -1;
    d_s1[i] = (pos1 < CAP) ? my_e1 * CAP + pos1 : -1;
}

// scatter: token rows -> dispatch buffer, fp16 (globals referenced in-kernel)
__global__ void scatter_kernel(const float* __restrict__ x) {
    int i = blockIdx.x;
    int s0 = d_s0[i], s1 = d_s1[i];
    if (s0 < 0 && s1 < 0) return;
    float4 v = ((const float4*)(x + (size_t)i * DIM))[threadIdx.x];
    uint2 hp = make_uint2(pack_h2(__float2half(v.x), __float2half(v.y)),
                          pack_h2(__float2half(v.z), __float2half(v.w)));
    if (s0 >= 0) ((uint2*)(d_disp16 + (size_t)s0 * DIM))[threadIdx.x] = hp;
    if (s1 >= 0) ((uint2*)(d_disp16 + (size_t)s1 * DIM))[threadIdx.x] = hp;
}

// weights: fp32 -> fp16, layout preserved; dst global selected by template
template<bool W1>
__global__ void wconv_kernel(const float* __restrict__ src) {
    __half* dst = W1 ? d_w1h : d_w2h;
    int i = blockIdx.x * blockDim.x + threadIdx.x;
    float2 v = ((const float2*)src)[i];
    ((uint32_t*)dst)[i] = pack_h2(__float2half(v.x), __float2half(v.y));
}

__device__ __forceinline__ float gelu_exact(float v) {
    return 0.5f * v * (1.0f + erff(v * 0.70710678118654752f));
}

// ---------------- mma.sync fp16 GEMM, double-buffered, 2 CTA/SM -------------
// Block tile 128x128, 8 warps (warp 64m x 32n), K-chunk 32, TWO smem stages
// (37.4 KB static), one __syncthreads per chunk, LDG.128 register prefetch.
// A fp16 [m][k] (disp16 or h16); B fp16 [e][k][n] (w1h/w2h). fp32 accum.
#define KC    32
#define A_ST  40     // halves per A row (80 B; 16B-aligned, LDSM conflict-free)
#define B_ST  136    // halves per B row (272 B; 16B-aligned, LDSM conflict-free)
#define A_HB  (128 * A_ST)   // 5120 halves / stage
#define B_HB  (KC * B_ST)    // 4352 halves / stage

template<int KTOT, int NTOT, bool FC1>
__global__ void __launch_bounds__(256, 2)
mma_gemm_kernel(const float* __restrict__ bias) {
    __shared__ __half sA[2][A_HB];   // 20480 B
    __shared__ __half sB[2][B_HB];   // 17408 B  (37888 B static total)

    const __half* __restrict__ Ag = FC1 ? d_disp16 : d_h16;
    const __half* __restrict__ Bg = FC1 ? d_w1h    : d_w2h;

    int tid = threadIdx.x;
    int wid = tid >> 5, lane = tid & 31;
    int wm = wid & 1, wn = wid >> 1;          // warp tile 64m x 32n

    int row0 = blockIdx.y * 128;
    int n0   = blockIdx.x * 128;
    int e    = row0 / CAP;                    // 128 | CAP
    const __half* Ap = Ag + (size_t)row0 * KTOT;
    const __half* Bp = Bg + (size_t)e * KTOT * NTOT;
    const float*  bp = bias + (size_t)e * NTOT;

    uint32_t aA[2] = { smem_u32(sA[0]), smem_u32(sA[1]) };
    uint32_t aB[2] = { smem_u32(sB[0]), smem_u32(sB[1]) };

    float acc[4][4][4];
#pragma unroll
    for (int mi = 0; mi < 4; mi++)
#pragma unroll
        for (int ni = 0; ni < 4; ni++)
#pragma unroll
            for (int q = 0; q < 4; q++) acc[mi][ni][q] = 0.0f;

    // load coords (per chunk = 512 vec8 each for A and B, 2 per thread):
    // A: rows 0..63 / 64..127, 4 vec8 per row
    const int arow = tid >> 2, acol = (tid & 3) * 8;
    // B: 32 k-rows, 16 vec8 per row (cols 0..63 / 64..127)
    const int brow = tid >> 3, bcol = (tid & 7) * 8;

    constexpr int NCH = KTOT / KC;

    uint4 aReg[2], bReg[2];
#pragma unroll
    for (int it = 0; it < 2; it++)
        aReg[it] = *(const uint4*)(Ap + (size_t)(arow + it * 64) * KTOT + acol);
#pragma unroll
    for (int it = 0; it < 2; it++)
        bReg[it] = *(const uint4*)(Bp + (size_t)brow * NTOT + n0 + bcol + it * 64);

    for (int ch = 0; ch < NCH; ch++) {
        int b = ch & 1;
        // ---- store prefetched regs -> smem stage b ----
#pragma unroll
        for (int it = 0; it < 2; it++)
            *(uint4*)&sA[b][(arow + it * 64) * A_ST + acol] = aReg[it];
#pragma unroll
        for (int it = 0; it < 2; it++)
            *(uint4*)&sB[b][brow * B_ST + bcol + it * 64] = bReg[it];
        __syncthreads();

        // ---- prefetch next chunk (LDG in flight over compute) ----
        if (ch + 1 < NCH) {
            int kn = (ch + 1) * KC;
#pragma unroll
            for (int it = 0; it < 2; it++)
                aReg[it] = *(const uint4*)(Ap + (size_t)(arow + it * 64) * KTOT + kn + acol);
#pragma unroll
            for (int it = 0; it < 2; it++)
                bReg[it] = *(const uint4*)(Bp + (size_t)(kn + brow) * NTOT + n0 + bcol + it * 64);
        }

        // ---- compute: 2 k16 steps ----
#pragma unroll
        for (int ks = 0; ks < 2; ks++) {
            uint32_t af[4][4];
#pragma unroll
            for (int mi = 0; mi < 4; mi++) {
                int r = wm * 64 + mi * 16 + (lane & 15);
                uint32_t off = (uint32_t)(r * (A_ST * 2) + ks * 32 + ((lane >> 4) << 4));
                ldmat_x4(af[mi], aA[b] + off);
            }
#pragma unroll
            for (int p = 0; p < 2; p++) {
                int j = lane >> 3, i = lane & 7;
                int kk = ks * 16 + (j & 1) * 8 + i;
                int nn = wn * 32 + p * 16 + (j >> 1) * 8;
                uint32_t off = (uint32_t)(kk * (B_ST * 2) + nn * 2);
                uint32_t b4[4];
                ldmat_x4_t(b4, aB[b] + off);
#pragma unroll
                for (int ni2 = 0; ni2 < 2; ni2++) {
                    int ni = p * 2 + ni2;
                    const uint32_t* bp2 = &b4[ni2 * 2];
#pragma unroll
                    for (int mi = 0; mi < 4; mi++)
                        mma16816(acc[mi][ni], af[mi], bp2);
                }
            }
        }
        // no trailing sync: next store targets the other stage; the sync at
        // the top of chunk ch+1 fences its last readers (chunk ch-1).
    }

    // ---- epilogue: bias (+gelu for FC1) ----
#pragma unroll
    for (int mi = 0; mi < 4; mi++) {
        int rbase = row0 + wm * 64 + mi * 16 + (lane >> 2);
#pragma unroll
        for (int ni = 0; ni < 4; ni++) {
            int col_l = wn * 32 + ni * 8 + ((lane & 3) << 1);
            float b0 = bp[n0 + col_l], b1 = bp[n0 + col_l + 1];
#pragma unroll
            for (int hh = 0; hh < 2; hh++) {
                int row = rbase + hh * 8;
                float v0 = acc[mi][ni][hh * 2]     + b0;
                float v1 = acc[mi][ni][hh * 2 + 1] + b1;
                size_t g = (size_t)row * NTOT + n0 + col_l;
                if (FC1) {
                    v0 = gelu_exact(v0); v1 = gelu_exact(v1);
                    *(uint32_t*)(d_h16 + g) =
                        pack_h2(__float2half(v0), __float2half(v1));
                } else {
                    *(float2*)(d_y + g) = make_float2(v0, v1);
                }
            }
        }
    }
}

// out[i] = w0 * Y[s0] + w1 * Y[s1]
__global__ void combine_kernel(float* __restrict__ out) {
    int i = blockIdx.x;
    int s0 = d_s0[i], s1 = d_s1[i];
    float w0 = (s0 >= 0) ? d_g0[i] : 0.0f;
    float w1 = (s1 >= 0) ? d_g1[i] : 0.0f;
    float4 r = make_float4(0.f, 0.f, 0.f, 0.f);
    if (s0 >= 0) {
        float4 a = ((const float4*)(d_y + (size_t)s0 * DIM))[threadIdx.x];
        r.x += w0 * a.x; r.y += w0 * a.y; r.z += w0 * a.z; r.w += w0 * a.w;
    }
    if (s1 >= 0) {
        float4 a = ((const float4*)(d_y + (size_t)s1 * DIM))[threadIdx.x];
        r.x += w1 * a.x; r.y += w1 * a.y; r.z += w1 * a.z; r.w += w1 * a.w;
    }
    ((float4*)(out + (size_t)i * DIM))[threadIdx.x] = r;
}

__global__ void laux_kernel(float* __restrict__ out, int out_size) {
    if (threadIdx.x == 0 && out_size > NTOK * DIM) {
        float lx = 0.0f;
        for (int e = 0; e < NEXP; e++) {
            float me = d_me[e] / (float)NTOK;
            float ce = (float)d_cnt0[e] / (float)NTOK;
            lx += me * ce;
        }
        out[NTOK * DIM] = lx * (float)NEXP;
    }
}

// ---------------- launch ---------------------------------------------------
extern "C" void kernel_launch(void* const* d_in, const int* in_sizes, int n_in,
                              void* d_out, int out_size) {
    const float* x     = (const float*)d_in[0];
    const float* wg    = (const float*)d_in[1];
    const float* fc1_w = (const float*)d_in[2];
    const float* fc1_b = (const float*)d_in[3];
    const float* fc2_w = (const float*)d_in[4];
    const float* fc2_b = (const float*)d_in[5];
    float* out = (float*)d_out;

    zero_small_kernel<<<1, 32>>>();
    gate_kernel<<<NTOK / 8, 256>>>(x, wg);
    rank_kernel<<<NTOK / 256, 256>>>();
    scatter_kernel<<<NTOK, 256>>>(x);

    const int wtot2 = NEXP * DIM * HID / 2;
    wconv_kernel<true ><<<wtot2 / 256, 256>>>(fc1_w);
    wconv_kernel<false><<<wtot2 / 256, 256>>>(fc2_w);

    // FC1: A=disp16 [EC][DIM], B=w1h [E][DIM][HID] -> h16 (bias+gelu)
    mma_gemm_kernel<DIM, HID, true><<<dim3(HID / 128, EC / 128), 256>>>(fc1_b);
    // FC2: A=h16 [EC][HID], B=w2h [E][HID][DIM] -> y fp32 (bias)
    mma_gemm_kernel<HID, DIM, false><<<dim3(DIM / 128, EC / 128), 256>>>(fc2_b);

    combine_kernel<<<NTOK, 256>>>(out);
    laux_kernel<<<1, 32>>>(out, out_size);
}

// round 17
// speedup vs baseline: 1.3542x; 1.0929x over previous
#include <cuda_runtime.h>
#include <cuda_fp16.h>
#include <math.h>
#include <stdint.h>

// Problem constants (fixed by setup_inputs)
#define NTOK 8192
#define DIM  1024
#define HID  4096
#define NEXP 8
#define CAP  2560              // int(2 * 1.25 * 8192 / 8)
#define EC   (NEXP * CAP)      // 20480 dispatch rows

// ---------------- scratch (static __device__ globals; no allocs) -----------
// NOTE: __device__ globals are ONLY referenced inside device code (passing
// them as host-side kernel args passes the host shadow address — root cause
// of the round-5/7/10/12 zero-output failures).
__device__ __align__(16) __half d_disp16[(size_t)EC * DIM];      // 40 MB
__device__ __align__(16) __half d_h16[(size_t)EC * HID];         // 168 MB
__device__ __align__(16) float  d_y[(size_t)EC * DIM];           // 80 MB
__device__ __align__(16) __half d_w1h[(size_t)NEXP * DIM * HID]; // 64 MB [e][k][n]
__device__ __align__(16) __half d_w2h[(size_t)NEXP * DIM * HID]; // 64 MB [e][k][n]

__device__ int   d_e0[NTOK], d_e1[NTOK];
__device__ float d_g0[NTOK], d_g1[NTOK];
__device__ int   d_s0[NTOK], d_s1[NTOK];     // dispatch slot or -1
__device__ float d_me[NEXP];                 // sum of softmax scores per expert
__device__ int   d_cnt0[NEXP];               // top-1 histogram (uncapped)
__device__ int   d_cnt1[NEXP];               // top-2 histogram (uncapped)

// ---------------- PTX helpers ----------------------------------------------
__device__ __forceinline__ uint32_t smem_u32(const void* p) {
    uint32_t a;
    asm("{ .reg .u64 t; cvta.to.shared.u64 t, %1; cvt.u32.u64 %0, t; }"
        : "=r"(a) : "l"(p));
    return a;
}
__device__ __forceinline__ void ldmat_x4(uint32_t* r, uint32_t addr) {
    asm volatile("ldmatrix.sync.aligned.m8n8.x4.shared.b16 {%0,%1,%2,%3}, [%4];"
                 : "=r"(r[0]), "=r"(r[1]), "=r"(r[2]), "=r"(r[3]) : "r"(addr));
}
__device__ __forceinline__ void ldmat_x4_t(uint32_t* r, uint32_t addr) {
    asm volatile("ldmatrix.sync.aligned.m8n8.x4.trans.shared.b16 {%0,%1,%2,%3}, [%4];"
                 : "=r"(r[0]), "=r"(r[1]), "=r"(r[2]), "=r"(r[3]) : "r"(addr));
}
__device__ __forceinline__ void mma16816(float* c, const uint32_t* a, const uint32_t* b) {
    asm volatile(
        "mma.sync.aligned.m16n8k16.row.col.f32.f16.f16.f32 "
        "{%0,%1,%2,%3}, {%4,%5,%6,%7}, {%8,%9}, {%0,%1,%2,%3};"
        : "+f"(c[0]), "+f"(c[1]), "+f"(c[2]), "+f"(c[3])
        : "r"(a[0]), "r"(a[1]), "r"(a[2]), "r"(a[3]), "r"(b[0]), "r"(b[1]));
}
__device__ __forceinline__ uint32_t pack_h2(__half a, __half b) {
    return (uint32_t)__half_as_ushort(a) | ((uint32_t)__half_as_ushort(b) << 16);
}

// ---------------- small kernels --------------------------------------------
__global__ void zero_small_kernel() {
    int t = threadIdx.x;
    if (t < NEXP) { d_me[t] = 0.0f; d_cnt0[t] = 0; d_cnt1[t] = 0; }
}

__global__ void gate_kernel(const float* __restrict__ x,
                            const float* __restrict__ wg) {
    int warp = (blockIdx.x * blockDim.x + threadIdx.x) >> 5;
    int lane = threadIdx.x & 31;
    if (warp >= NTOK) return;

    const float* xr = x + (size_t)warp * DIM;
    float acc[NEXP];
#pragma unroll
    for (int e = 0; e < NEXP; e++) acc[e] = 0.0f;
    for (int d = lane; d < DIM; d += 32) {
        float xv = xr[d];
        const float* w = wg + (size_t)d * NEXP;
#pragma unroll
        for (int e = 0; e < NEXP; e++) acc[e] += xv * w[e];
    }
#pragma unroll
    for (int off = 16; off > 0; off >>= 1)
#pragma unroll
        for (int e = 0; e < NEXP; e++)
            acc[e] += __shfl_xor_sync(0xFFFFFFFFu, acc[e], off);

    if (lane == 0) {
        float m = acc[0];
#pragma unroll
        for (int e = 1; e < NEXP; e++) m = fmaxf(m, acc[e]);
        float p[NEXP], s = 0.0f;
#pragma unroll
        for (int e = 0; e < NEXP; e++) { p[e] = expf(acc[e] - m); s += p[e]; }
        float inv = 1.0f / s;
#pragma unroll
        for (int e = 0; e < NEXP; e++) p[e] *= inv;

        float best = -1.0f, second = -1.0f;
        int e0 = 0, e1 = 0;
#pragma unroll
        for (int e = 0; e < NEXP; e++) {
            float v = p[e];
            if (v > best)        { second = best; e1 = e0; best = v; e0 = e; }
            else if (v > second) { second = v; e1 = e; }
        }
        d_e0[warp] = e0; d_e1[warp] = e1;
        d_g0[warp] = best; d_g1[warp] = second;
#pragma unroll
        for (int e = 0; e < NEXP; e++) atomicAdd(&d_me[e], p[e]);
        atomicAdd(&d_cnt0[e0], 1);
        atomicAdd(&d_cnt1[e1], 1);
    }
}

__global__ void rank_kernel() {
    __shared__ int   se0[256]; __shared__ float sg0[256];
    __shared__ int   se1[256]; __shared__ float sg1[256];

    int i = blockIdx.x * 256 + threadIdx.x;
    int   my_e0 = d_e0[i], my_e1 = d_e1[i];
    float my_g0 = d_g0[i], my_g1 = d_g1[i];
    int r0 = 0, r1 = 0;

    for (int base = 0; base < NTOK; base += 256) {
        int t = base + threadIdx.x;
        se0[threadIdx.x] = d_e0[t]; sg0[threadIdx.x] = d_g0[t];
        se1[threadIdx.x] = d_e1[t]; sg1[threadIdx.x] = d_g1[t];
        __syncthreads();
#pragma unroll 8
        for (int k = 0; k < 256; k++) {
            int tp = base + k;
            r0 += (se0[k] == my_e0) && (sg0[k] > my_g0 || (sg0[k] == my_g0 && tp < i));
            r1 += (se1[k] == my_e1) && (sg1[k] > my_g1 || (sg1[k] == my_g1 && tp < i));
        }
        __syncthreads();
    }
    int pos0 = r0;
    int pos1 = r1 + d_cnt0[my_e1];
    d_s0[i] = (pos0 < CAP) ? my_e0 * CAP + pos0 : -1;
    d_s1[i] = (pos1 < CAP) ? my_e1 * CAP + pos1 : -1;
}

// scatter: token rows -> dispatch buffer, fp16 (globals referenced in-kernel)
__global__ void scatter_kernel(const float* __restrict__ x) {
    int i = blockIdx.x;
    int s0 = d_s0[i], s1 = d_s1[i];
    if (s0 < 0 && s1 < 0) return;
    float4 v = ((const float4*)(x + (size_t)i * DIM))[threadIdx.x];
    uint2 hp = make_uint2(pack_h2(__float2half(v.x), __float2half(v.y)),
                          pack_h2(__float2half(v.z), __float2half(v.w)));
    if (s0 >= 0) ((uint2*)(d_disp16 + (size_t)s0 * DIM))[threadIdx.x] = hp;
    if (s1 >= 0) ((uint2*)(d_disp16 + (size_t)s1 * DIM))[threadIdx.x] = hp;
}

// weights: fp32 -> fp16, layout preserved; dst global selected by template
template<bool W1>
__global__ void wconv_kernel(const float* __restrict__ src) {
    __half* dst = W1 ? d_w1h : d_w2h;
    int i = blockIdx.x * blockDim.x + threadIdx.x;
    float2 v = ((const float2*)src)[i];
    ((uint32_t*)dst)[i] = pack_h2(__float2half(v.x), __float2half(v.y));
}

__device__ __forceinline__ float gelu_exact(float v) {
    return 0.5f * v * (1.0f + erff(v * 0.70710678118654752f));
}

// ---------------- mma.sync fp16 GEMM, double-buffered, 2 CTA/SM -------------
// Block tile 128x128, 8 warps (warp 64m x 32n), K-chunk 32, TWO smem stages
// (37.9 KB static), one __syncthreads per chunk, LDG.128 register prefetch.
// Tiles whose 128 rows lie entirely in unused capacity padding are skipped
// (valid slots always satisfy pos < cnt0[e]+cnt1[e]).
#define KC    32
#define A_ST  40     // halves per A row (80 B; 16B-aligned, LDSM conflict-free)
#define B_ST  136    // halves per B row (272 B; 16B-aligned, LDSM conflict-free)
#define A_HB  (128 * A_ST)   // 5120 halves / stage
#define B_HB  (KC * B_ST)    // 4352 halves / stage

template<int KTOT, int NTOT, bool FC1>
__global__ void __launch_bounds__(256, 2)
mma_gemm_kernel(const float* __restrict__ bias) {
    __shared__ __half sA[2][A_HB];   // 20480 B
    __shared__ __half sB[2][B_HB];   // 17408 B  (37888 B static total)

    const __half* __restrict__ Ag = FC1 ? d_disp16 : d_h16;
    const __half* __restrict__ Bg = FC1 ? d_w1h    : d_w2h;

    int tid = threadIdx.x;
    int wid = tid >> 5, lane = tid & 31;
    int wm = wid & 1, wn = wid >> 1;          // warp tile 64m x 32n

    int row0 = blockIdx.y * 128;
    int n0   = blockIdx.x * 128;
    int e    = row0 / CAP;                    // 128 | CAP
    // skip tiles entirely inside unused capacity padding
    int used = d_cnt0[e] + d_cnt1[e];
    if (used > CAP) used = CAP;
    if (row0 - e * CAP >= used) return;

    const __half* Ap = Ag + (size_t)row0 * KTOT;
    const __half* Bp = Bg + (size_t)e * KTOT * NTOT;
    const float*  bp = bias + (size_t)e * NTOT;

    uint32_t aA[2] = { smem_u32(sA[0]), smem_u32(sA[1]) };
    uint32_t aB[2] = { smem_u32(sB[0]), smem_u32(sB[1]) };

    float acc[4][4][4];
#pragma unroll
    for (int mi = 0; mi < 4; mi++)
#pragma unroll
        for (int ni = 0; ni < 4; ni++)
#pragma unroll
            for (int q = 0; q < 4; q++) acc[mi][ni][q] = 0.0f;

    // load coords (per chunk = 512 vec8 each for A and B, 2 per thread):
    const int arow = tid >> 2, acol = (tid & 3) * 8;
    const int brow = tid >> 3, bcol = (tid & 7) * 8;

    constexpr int NCH = KTOT / KC;

    uint4 aReg[2], bReg[2];
#pragma unroll
    for (int it = 0; it < 2; it++)
        aReg[it] = *(const uint4*)(Ap + (size_t)(arow + it * 64) * KTOT + acol);
#pragma unroll
    for (int it = 0; it < 2; it++)
        bReg[it] = *(const uint4*)(Bp + (size_t)brow * NTOT + n0 + bcol + it * 64);

    for (int ch = 0; ch < NCH; ch++) {
        int b = ch & 1;
        // ---- store prefetched regs -> smem stage b ----
#pragma unroll
        for (int it = 0; it < 2; it++)
            *(uint4*)&sA[b][(arow + it * 64) * A_ST + acol] = aReg[it];
#pragma unroll
        for (int it = 0; it < 2; it++)
            *(uint4*)&sB[b][brow * B_ST + bcol + it * 64] = bReg[it];
        __syncthreads();

        // ---- prefetch next chunk (LDG in flight over compute) ----
        if (ch + 1 < NCH) {
            int kn = (ch + 1) * KC;
#pragma unroll
            for (int it = 0; it < 2; it++)
                aReg[it] = *(const uint4*)(Ap + (size_t)(arow + it * 64) * KTOT + kn + acol);
#pragma unroll
            for (int it = 0; it < 2; it++)
                bReg[it] = *(const uint4*)(Bp + (size_t)(kn + brow) * NTOT + n0 + bcol + it * 64);
        }

        // ---- compute: 2 k16 steps ----
#pragma unroll
        for (int ks = 0; ks < 2; ks++) {
            uint32_t af[4][4];
#pragma unroll
            for (int mi = 0; mi < 4; mi++) {
                int r = wm * 64 + mi * 16 + (lane & 15);
                uint32_t off = (uint32_t)(r * (A_ST * 2) + ks * 32 + ((lane >> 4) << 4));
                ldmat_x4(af[mi], aA[b] + off);
            }
#pragma unroll
            for (int p = 0; p < 2; p++) {
                int j = lane >> 3, i = lane & 7;
                int kk = ks * 16 + (j & 1) * 8 + i;
                int nn = wn * 32 + p * 16 + (j >> 1) * 8;
                uint32_t off = (uint32_t)(kk * (B_ST * 2) + nn * 2);
                uint32_t b4[4];
                ldmat_x4_t(b4, aB[b] + off);
#pragma unroll
                for (int ni2 = 0; ni2 < 2; ni2++) {
                    int ni = p * 2 + ni2;
                    const uint32_t* bp2 = &b4[ni2 * 2];
#pragma unroll
                    for (int mi = 0; mi < 4; mi++)
                        mma16816(acc[mi][ni], af[mi], bp2);
                }
            }
        }
        // no trailing sync: next store targets the other stage; the sync at
        // the top of chunk ch+1 fences its last readers (chunk ch-1).
    }

    // ---- epilogue: bias (+gelu for FC1) ----
#pragma unroll
    for (int mi = 0; mi < 4; mi++) {
        int rbase = row0 + wm * 64 + mi * 16 + (lane >> 2);
#pragma unroll
        for (int ni = 0; ni < 4; ni++) {
            int col_l = wn * 32 + ni * 8 + ((lane & 3) << 1);
            float b0 = bp[n0 + col_l], b1 = bp[n0 + col_l + 1];
#pragma unroll
            for (int hh = 0; hh < 2; hh++) {
                int row = rbase + hh * 8;
                float v0 = acc[mi][ni][hh * 2]     + b0;
                float v1 = acc[mi][ni][hh * 2 + 1] + b1;
                size_t g = (size_t)row * NTOT + n0 + col_l;
                if (FC1) {
                    v0 = gelu_exact(v0); v1 = gelu_exact(v1);
                    *(uint32_t*)(d_h16 + g) =
                        pack_h2(__float2half(v0), __float2half(v1));
                } else {
                    *(float2*)(d_y + g) = make_float2(v0, v1);
                }
            }
        }
    }
}

// out[i] = w0 * Y[s0] + w1 * Y[s1]
__global__ void combine_kernel(float* __restrict__ out) {
    int i = blockIdx.x;
    int s0 = d_s0[i], s1 = d_s1[i];
    float w0 = (s0 >= 0) ? d_g0[i] : 0.0f;
    float w1 = (s1 >= 0) ? d_g1[i] : 0.0f;
    float4 r = make_float4(0.f, 0.f, 0.f, 0.f);
    if (s0 >= 0) {
        float4 a = ((const float4*)(d_y + (size_t)s0 * DIM))[threadIdx.x];
        r.x += w0 * a.x; r.y += w0 * a.y; r.z += w0 * a.z; r.w += w0 * a.w;
    }
    if (s1 >= 0) {
        float4 a = ((const float4*)(d_y + (size_t)s1 * DIM))[threadIdx.x];
        r.x += w1 * a.x; r.y += w1 * a.y; r.z += w1 * a.z; r.w += w1 * a.w;
    }
    ((float4*)(out + (size_t)i * DIM))[threadIdx.x] = r;
}

__global__ void laux_kernel(float* __restrict__ out, int out_size) {
    if (threadIdx.x == 0 && out_size > NTOK * DIM) {
        float lx = 0.0f;
        for (int e = 0; e < NEXP; e++) {
            float me = d_me[e] / (float)NTOK;
            float ce = (float)d_cnt0[e] / (float)NTOK;
            lx += me * ce;
        }
        out[NTOK * DIM] = lx * (float)NEXP;
    }
}

// ---------------- launch ---------------------------------------------------
extern "C" void kernel_launch(void* const* d_in, const int* in_sizes, int n_in,
                              void* d_out, int out_size) {
    const float* x     = (const float*)d_in[0];
    const float* wg    = (const float*)d_in[1];
    const float* fc1_w = (const float*)d_in[2];
    const float* fc1_b = (const float*)d_in[3];
    const float* fc2_w = (const float*)d_in[4];
    const float* fc2_b = (const float*)d_in[5];
    float* out = (float*)d_out;

    zero_small_kernel<<<1, 32>>>();
    gate_kernel<<<NTOK / 8, 256>>>(x, wg);
    rank_kernel<<<NTOK / 256, 256>>>();
    scatter_kernel<<<NTOK, 256>>>(x);

    const int wtot2 = NEXP * DIM * HID / 2;
    wconv_kernel<true ><<<wtot2 / 256, 256>>>(fc1_w);
    wconv_kernel<false><<<wtot2 / 256, 256>>>(fc2_w);

    // FC1: A=disp16 [EC][DIM], B=w1h [E][DIM][HID] -> h16 (bias+gelu)
    mma_gemm_kernel<DIM, HID, true><<<dim3(HID / 128, EC / 128), 256>>>(fc1_b);
    // FC2: A=h16 [EC][HID], B=w2h [E][HID][DIM] -> y fp32 (bias)
    mma_gemm_kernel<HID, DIM, false><<<dim3(DIM / 128, EC / 128), 256>>>(fc2_b);

    combine_kernel<<<NTOK, 256>>>(out);
    laux_kernel<<<1, 32>>>(out, out_size);
}